// round 1
// baseline (speedup 1.0000x reference)
#include <cuda_runtime.h>
#include <cstdint>

// Problem constants
#define BB   8
#define CC   128
#define HH   256
#define WW   256
#define OO   128
#define HWP  (HH*WW)          // 65536
#define MTOT (BB*HWP)         // 524288
#define MTILE 64
#define NTHREADS 256
#define EPSV 1e-6f

// SMEM layout (in float2 units), k-paired: kp = (k>>3)*4 + (k&3), .x = k_lo, .y = k_lo+4
// rows padded to 65 float2 to dodge bank conflicts
#define KPW 65
#define SA_A 0                      // [64][65]  act tile
#define SA_G (64*KPW)               // [64][65]  g tile
#define SW_X (2*64*KPW)             // [128][65] wx
#define SW_Y (2*64*KPW + 128*KPW)   // [128][65] wy
#define SMEM_F2 (2*64*KPW + 2*128*KPW)   // 24960 float2 = 199680 B

__device__ __forceinline__ float tf32r(float f) {
    uint32_t u;
    asm("cvt.rna.tf32.f32 %0, %1;" : "=r"(u) : "f"(f));
    return __uint_as_float(u);
}

__device__ __forceinline__ void mma_tf32(float* c,
                                         uint32_t a0, uint32_t a1, uint32_t a2, uint32_t a3,
                                         uint32_t b0, uint32_t b1) {
    asm volatile(
        "mma.sync.aligned.m16n8k8.row.col.f32.tf32.tf32.f32 "
        "{%0,%1,%2,%3},{%4,%5,%6,%7},{%8,%9},{%0,%1,%2,%3};\n"
        : "+f"(c[0]), "+f"(c[1]), "+f"(c[2]), "+f"(c[3])
        : "r"(a0), "r"(a1), "r"(a2), "r"(a3), "r"(b0), "r"(b1));
}

__global__ __launch_bounds__(NTHREADS, 1)
void avnn_kernel(const float* __restrict__ x,
                 const float* __restrict__ wx,
                 const float* __restrict__ bx,
                 const float* __restrict__ wy,
                 const float* __restrict__ by,
                 float2* __restrict__ out) {
    extern __shared__ float2 smem[];
    float2* sAa = smem + SA_A;
    float2* sAg = smem + SA_G;
    float2* sWx = smem + SW_X;
    float2* sWy = smem + SW_Y;
    float* sAaF = (float*)sAa;
    float* sAgF = (float*)sAg;
    float* sWxF = (float*)sWx;
    float* sWyF = (float*)sWy;

    const int tid = threadIdx.x;

    // ---- Stage weights (tf32-rounded) into paired layout ----
    #pragma unroll 4
    for (int idx = tid; idx < OO * CC; idx += NTHREADS) {
        int o = idx >> 7;
        int c = idx & 127;
        int k8 = c >> 3, r = c & 7, hi = r >> 2, qq = r & 3;
        int kp = k8 * 4 + qq;
        int so = (o * KPW + kp) * 2 + hi;
        sWxF[so] = tf32r(wx[idx]);
        sWyF[so] = tf32r(wy[idx]);
    }

    // ---- Stage x tile: compute g = a*c/(|a|+eps), tf32-round both ----
    const int m0 = blockIdx.x * MTILE;
    const int b  = m0 >> 16;          // HWP = 65536
    const int p0 = m0 & (HWP - 1);
    const float2* xv = (const float2*)x;

    #pragma unroll 4
    for (int idx = tid; idx < MTILE * CC; idx += NTHREADS) {
        int c = idx >> 6;
        int m = idx & (MTILE - 1);
        float2 v = xv[(size_t)(b * CC + c) * HWP + p0 + m];
        float a = v.x, cr = v.y;
        float g = __fdividef(a * cr, fabsf(a) + EPSV);
        int k8 = c >> 3, r = c & 7, hi = r >> 2, qq = r & 3;
        int kp = k8 * 4 + qq;
        int so = (m * KPW + kp) * 2 + hi;
        sAaF[so] = tf32r(a);
        sAgF[so] = tf32r(g);
    }

    __syncthreads();

    // ---- Compute: 8 warps = 4 (M) x 2 (N). Warp tile: 16 pix x 64 O, K=128, both gemms ----
    const int warp = tid >> 5, lane = tid & 31;
    const int gid = lane >> 2, q = lane & 3;
    const int m_off = (warp & 3) * 16;
    const int n_off = (warp >> 2) * 64;

    float acc_a[8][4];
    float acc_g[8][4];
    #pragma unroll
    for (int nt = 0; nt < 8; nt++)
        #pragma unroll
        for (int i = 0; i < 4; i++) { acc_a[nt][i] = 0.f; acc_g[nt][i] = 0.f; }

    #pragma unroll
    for (int k8 = 0; k8 < 16; k8++) {
        const int kp = k8 * 4 + q;
        float2 Aa0 = sAa[(m_off + gid) * KPW + kp];
        float2 Aa1 = sAa[(m_off + gid + 8) * KPW + kp];
        float2 Ag0 = sAg[(m_off + gid) * KPW + kp];
        float2 Ag1 = sAg[(m_off + gid + 8) * KPW + kp];
        uint32_t aa0 = __float_as_uint(Aa0.x), aa1 = __float_as_uint(Aa1.x);
        uint32_t aa2 = __float_as_uint(Aa0.y), aa3 = __float_as_uint(Aa1.y);
        uint32_t ag0 = __float_as_uint(Ag0.x), ag1 = __float_as_uint(Ag1.x);
        uint32_t ag2 = __float_as_uint(Ag0.y), ag3 = __float_as_uint(Ag1.y);

        #pragma unroll
        for (int nt = 0; nt < 8; nt++) {
            int n = n_off + nt * 8 + gid;
            float2 Bx2 = sWx[n * KPW + kp];
            float2 By2 = sWy[n * KPW + kp];
            mma_tf32(acc_a[nt], aa0, aa1, aa2, aa3,
                     __float_as_uint(Bx2.x), __float_as_uint(Bx2.y));
            mma_tf32(acc_g[nt], ag0, ag1, ag2, ag3,
                     __float_as_uint(By2.x), __float_as_uint(By2.y));
        }
    }

    // ---- Epilogue: bias + relu, interleaved float2 store {act, carry} ----
    const size_t obase = (size_t)b * OO * HWP + p0;
    #pragma unroll
    for (int nt = 0; nt < 8; nt++) {
        const int o_base = n_off + nt * 8 + 2 * q;
        #pragma unroll
        for (int i = 0; i < 4; i++) {
            int o  = o_base + (i & 1);
            int mr = m_off + gid + (i >> 1) * 8;
            float av = fmaxf(acc_a[nt][i] + __ldg(bx + o), 0.f);
            float cv = acc_g[nt][i] + __ldg(by + o);
            out[obase + (size_t)o * HWP + mr] = make_float2(av, cv);
        }
    }
}

extern "C" void kernel_launch(void* const* d_in, const int* in_sizes, int n_in,
                              void* d_out, int out_size) {
    const float* x  = (const float*)d_in[0];
    const float* wx = (const float*)d_in[1];
    const float* bx = (const float*)d_in[2];
    const float* wy = (const float*)d_in[3];
    const float* by = (const float*)d_in[4];
    float2* out = (float2*)d_out;

    const size_t smem_bytes = SMEM_F2 * sizeof(float2);  // 199680
    cudaFuncSetAttribute(avnn_kernel, cudaFuncAttributeMaxDynamicSharedMemorySize,
                         (int)smem_bytes);

    dim3 grid(MTOT / MTILE);   // 8192
    dim3 block(NTHREADS);      // 256
    avnn_kernel<<<grid, block, smem_bytes>>>(x, wx, bx, wy, by, out);
}

// round 3
// speedup vs baseline: 3.8160x; 3.8160x over previous
#include <cuda_runtime.h>
#include <cstdint>

#define NTILES 8192            // 524288 pixels / 64 per tile
#define EPSV   1e-6f

// smem layout in float2 units
// sAa [64][64], sAg [64][64], sWx [128][64], sWy [128][64]
#define OFF_AG 4096
#define OFF_WX 8192
#define OFF_WY 16384
#define SMEM_F2 24576           // 196608 bytes

__device__ __forceinline__ float tf32r(float f) {
    uint32_t u; asm("cvt.rna.tf32.f32 %0, %1;" : "=r"(u) : "f"(f));
    return __uint_as_float(u);
}

__device__ __forceinline__ void mma_tf32(float* c, float2 a_lo, float2 a_hi, float2 b) {
    // a0 = A[gid][kq]     (a_lo.x), a1 = A[gid+8][kq]   (a_hi.x)
    // a2 = A[gid][kq+4]   (a_lo.y), a3 = A[gid+8][kq+4] (a_hi.y)
    asm volatile(
        "mma.sync.aligned.m16n8k8.row.col.f32.tf32.tf32.f32 "
        "{%0,%1,%2,%3},{%4,%5,%6,%7},{%8,%9},{%0,%1,%2,%3};\n"
        : "+f"(c[0]), "+f"(c[1]), "+f"(c[2]), "+f"(c[3])
        : "r"(__float_as_uint(a_lo.x)), "r"(__float_as_uint(a_hi.x)),
          "r"(__float_as_uint(a_lo.y)), "r"(__float_as_uint(a_hi.y)),
          "r"(__float_as_uint(b.x)),    "r"(__float_as_uint(b.y)));
}

__global__ __launch_bounds__(256, 1)
void avnn_p(const float* __restrict__ x,
            const float* __restrict__ wx,
            const float* __restrict__ bx,
            const float* __restrict__ wy,
            const float* __restrict__ by,
            float2* __restrict__ out) {
    extern __shared__ float2 smem[];
    float2* sAa = smem;
    float2* sAg = smem + OFF_AG;
    float2* sWx = smem + OFF_WX;
    float2* sWy = smem + OFF_WY;

    const int tid = threadIdx.x, wid = tid >> 5, lane = tid & 31;
    const int gid = lane >> 2, q = lane & 3;

    // ---- stage weights once (tf32, swizzled) ----
    #pragma unroll 4
    for (int idx = tid; idx < 128 * 128; idx += 256) {
        int n = idx >> 7, c = idx & 127;
        int k8 = c >> 3, qq = c & 3, hi = (c >> 2) & 1;
        int col = ((k8 ^ (n & 3)) << 2) | (qq ^ ((n >> 2) & 3));
        ((float*)&sWx[n * 64 + col])[hi] = tf32r(wx[idx]);
        ((float*)&sWy[n * 64 + col])[hi] = tf32r(wy[idx]);
    }

    // ---- per-thread constants ----
    const int mbase = (wid & 1) * 32;      // pixel base (2 M-warps)
    const int nbase = (wid >> 1) * 32;     // o base     (4 N-warps)
    const int g3 = gid & 3;

    float bxv[4][2], byv[4][2];
    #pragma unroll
    for (int nt = 0; nt < 4; nt++) {
        int o0 = nbase + nt * 8 + 2 * q;
        bxv[nt][0] = __ldg(bx + o0); bxv[nt][1] = __ldg(bx + o0 + 1);
        byv[nt][0] = __ldg(by + o0); byv[nt][1] = __ldg(by + o0 + 1);
    }

    // fragment row base pointers (contents change per tile, addresses don't)
    const int rA0 = mbase + gid, rA1 = mbase + gid + 8;
    const int nB0 = nbase + gid, nB1 = nbase + gid + 8;
    const float2* pa0 = sAa + rA0 * 64 + (q ^ ((rA0 >> 2) & 3));
    const float2* pa1 = sAa + rA1 * 64 + (q ^ ((rA1 >> 2) & 3));
    const float2* pb0 = sWx + nB0 * 64 + (q ^ ((nB0 >> 2) & 3));
    const float2* pb1 = sWx + nB1 * 64 + (q ^ ((nB1 >> 2) & 3));

    // staging constants (h-independent)
    const int px3 = lane & 3, pq = (lane >> 2) & 3;
    const float2* xv = (const float2*)x;
    const int grid = gridDim.x;

    int t = blockIdx.x;
    float2 rx[2][16];

    // prefetch first tile: warp wid owns c in [wid*16, wid*16+16), lane = pixel
    {
        int b = t >> 10, pp = (t & 1023) << 6;
        const float2* xb = xv + (((size_t)(b * 128 + wid * 16)) << 16) + pp + lane;
        #pragma unroll
        for (int j = 0; j < 16; j++) {
            rx[0][j] = __ldg(xb + ((size_t)j << 16));
            rx[1][j] = __ldg(xb + ((size_t)j << 16) + 32);
        }
    }

    for (;;) {
        // ---- transform + store tile t into smem ----
        #pragma unroll
        for (int h = 0; h < 2; h++) {
            const int p = lane + 32 * h;
            float2* pa = sAa + p * 64;
            float2* pg = sAg + p * 64;
            #pragma unroll
            for (int kg = 0; kg < 2; kg++) {
                const int chi = (((wid * 2 + kg) ^ px3) << 2);
                #pragma unroll
                for (int qq2 = 0; qq2 < 4; qq2++) {
                    float2 vlo = rx[h][kg * 8 + qq2];
                    float2 vhi = rx[h][kg * 8 + qq2 + 4];
                    float2 av, gv;
                    av.x = tf32r(vlo.x);
                    av.y = tf32r(vhi.x);
                    gv.x = tf32r(__fdividef(vlo.x * vlo.y, fabsf(vlo.x) + EPSV));
                    gv.y = tf32r(__fdividef(vhi.x * vhi.y, fabsf(vhi.x) + EPSV));
                    int col = chi | (qq2 ^ pq);
                    pa[col] = av;
                    pg[col] = gv;
                }
            }
        }
        __syncthreads();

        // ---- prefetch tile t+grid (latency hides under MMA below) ----
        const int tn = t + grid;
        if (tn < NTILES) {
            int b = tn >> 10, pp = (tn & 1023) << 6;
            const float2* xb = xv + (((size_t)(b * 128 + wid * 16)) << 16) + pp + lane;
            #pragma unroll
            for (int j = 0; j < 16; j++) {
                rx[0][j] = __ldg(xb + ((size_t)j << 16));
                rx[1][j] = __ldg(xb + ((size_t)j << 16) + 32);
            }
        }

        // ---- compute: warp tile 32 pix x 32 o, both gemms, K=128 ----
        float acc[2][2][4][4];
        #pragma unroll
        for (int g = 0; g < 2; g++)
            #pragma unroll
            for (int mt = 0; mt < 2; mt++)
                #pragma unroll
                for (int nt = 0; nt < 4; nt++)
                    #pragma unroll
                    for (int i = 0; i < 4; i++) acc[g][mt][nt][i] = 0.f;

        #pragma unroll
        for (int k8 = 0; k8 < 16; k8++) {
            const int d = (k8 ^ g3) << 2;
            const float2* A0 = pa0 + d;
            const float2* A1 = pa1 + d;
            const float2* B0 = pb0 + d;
            const float2* B1 = pb1 + d;

            float2 aa00 = A0[0],    aa01 = A1[0];      // mt0, rows gid / gid+8
            float2 aa10 = A0[1024], aa11 = A1[1024];   // mt1 (+16 rows)
            float2 ag00 = A0[OFF_AG],        ag01 = A1[OFF_AG];
            float2 ag10 = A0[OFF_AG + 1024], ag11 = A1[OFF_AG + 1024];

            float2 bx0 = B0[0],    bx1 = B1[0];        // nt0, nt1
            float2 bx2 = B0[1024], bx3 = B1[1024];     // nt2, nt3
            float2 by0 = B0[8192], by1 = B1[8192];     // sWy = sWx + 8192 f2
            float2 by2 = B0[9216], by3 = B1[9216];

            mma_tf32(acc[0][0][0], aa00, aa01, bx0);
            mma_tf32(acc[0][0][1], aa00, aa01, bx1);
            mma_tf32(acc[0][0][2], aa00, aa01, bx2);
            mma_tf32(acc[0][0][3], aa00, aa01, bx3);
            mma_tf32(acc[0][1][0], aa10, aa11, bx0);
            mma_tf32(acc[0][1][1], aa10, aa11, bx1);
            mma_tf32(acc[0][1][2], aa10, aa11, bx2);
            mma_tf32(acc[0][1][3], aa10, aa11, bx3);
            mma_tf32(acc[1][0][0], ag00, ag01, by0);
            mma_tf32(acc[1][0][1], ag00, ag01, by1);
            mma_tf32(acc[1][0][2], ag00, ag01, by2);
            mma_tf32(acc[1][0][3], ag00, ag01, by3);
            mma_tf32(acc[1][1][0], ag10, ag11, by0);
            mma_tf32(acc[1][1][1], ag10, ag11, by1);
            mma_tf32(acc[1][1][2], ag10, ag11, by2);
            mma_tf32(acc[1][1][3], ag10, ag11, by3);
        }

        // ---- epilogue: bias + relu, float2{act, carry} stores ----
        {
            const int b = t >> 10, pp = (t & 1023) << 6;
            const size_t tb = ((size_t)b << 23) + (size_t)pp;
            #pragma unroll
            for (int nt = 0; nt < 4; nt++) {
                const int o0 = nbase + nt * 8 + 2 * q;
                #pragma unroll
                for (int io = 0; io < 2; io++) {
                    float2* rowp = out + tb + ((size_t)(o0 + io) << 16);
                    #pragma unroll
                    for (int mt = 0; mt < 2; mt++) {
                        #pragma unroll
                        for (int ih = 0; ih < 2; ih++) {
                            const int pix = mbase + mt * 16 + gid + ih * 8;
                            float a = acc[0][mt][nt][ih * 2 + io] + bxv[nt][io];
                            float g = acc[1][mt][nt][ih * 2 + io] + byv[nt][io];
                            rowp[pix] = make_float2(fmaxf(a, 0.f), g);
                        }
                    }
                }
            }
        }

        if (tn >= NTILES) break;
        t = tn;
        __syncthreads();   // protect smem before next tile's stores
    }
}

extern "C" void kernel_launch(void* const* d_in, const int* in_sizes, int n_in,
                              void* d_out, int out_size) {
    const float* x  = (const float*)d_in[0];
    const float* wx = (const float*)d_in[1];
    const float* bx = (const float*)d_in[2];
    const float* wy = (const float*)d_in[3];
    const float* by = (const float*)d_in[4];
    float2* out = (float2*)d_out;

    int nsm = 148;
    cudaDeviceGetAttribute(&nsm, cudaDevAttrMultiProcessorCount, 0);

    const size_t smem_bytes = SMEM_F2 * sizeof(float2);   // 196608
    cudaFuncSetAttribute(avnn_p, cudaFuncAttributeMaxDynamicSharedMemorySize,
                         (int)smem_bytes);

    avnn_p<<<nsm, 256, smem_bytes>>>(x, wx, bx, wy, by, out);
}